// round 14
// baseline (speedup 1.0000x reference)
#include <cuda_runtime.h>
#include <cstdint>

// QINCo: D=128, M=8, K=256, L=2, H=256, BS=1024
#define Dq   128
#define Mq   8
#define Kq   256
#define Hq   256
#define BSq  1024
#define NROW (BSq * Kq)

#define OUT_CODES (BSq * Dq)
#define OUT_SIDE  (OUT_CODES + BSq * Mq)

// ---------------- device scratch (static, no allocs) ----------------
__device__ float g_xhat[BSq * Dq];
__device__ float g_CkAll[(Mq - 1) * Kq * Dq];    // per-m: cb + cb@Wz^T
__device__ float g_A0All[(Mq - 1) * Kq * Hq];    // per-m: Ck@W1_0^T
__device__ float g_Xb[BSq * Dq];
__device__ float g_B0[BSq * Hq];
__device__ float g_Z1[NROW * Dq];
__device__ float g_H1[NROW * Hq];
__device__ float g_ZF[NROW * Dq];
__device__ float g_dist[NROW];

// ---------------- packed f32x2 helpers ----------------
__device__ __forceinline__ void ffma2(unsigned long long& d, unsigned long long a, unsigned long long b) {
    asm("fma.rn.f32x2 %0, %1, %2, %0;" : "+l"(d) : "l"(a), "l"(b));
}
__device__ __forceinline__ unsigned long long bcast2(float v) {
    unsigned long long r;
    asm("mov.b64 %0, {%1, %1};" : "=l"(r) : "f"(v));
    return r;
}
__device__ __forceinline__ float2 unpk2(unsigned long long v) {
    float lo, hi;
    asm("mov.b64 {%0, %1}, %2;" : "=f"(lo), "=f"(hi) : "l"(v));
    return make_float2(lo, hi);
}

// ================= FFMA2 inner-product step (PROVEN in R9) =================
#define INNER_STEP(Rsrc, Wsrc)                                                  \
    do {                                                                        \
        float4 a0 = *(const float4*)(&Rsrc[h][ty * 8]);                         \
        float4 a1 = *(const float4*)(&Rsrc[h][ty * 8 + 4]);                     \
        ulonglong2 wv0 = *(const ulonglong2*)(&Wsrc[h][tx * 8]);                \
        ulonglong2 wv1 = *(const ulonglong2*)(&Wsrc[h][tx * 8 + 4]);            \
        unsigned long long ap[8] = {bcast2(a0.x), bcast2(a0.y), bcast2(a0.z),   \
                                    bcast2(a0.w), bcast2(a1.x), bcast2(a1.y),   \
                                    bcast2(a1.z), bcast2(a1.w)};                \
        unsigned long long wp[4] = {wv0.x, wv0.y, wv1.x, wv1.y};                \
        _Pragma("unroll")                                                       \
        for (int i = 0; i < 8; i++) {                                           \
            ffma2(acc[i][0], ap[i], wp[0]);                                     \
            ffma2(acc[i][1], ap[i], wp[1]);                                     \
            ffma2(acc[i][2], ap[i], wp[2]);                                     \
            ffma2(acc[i][3], ap[i], wp[3]);                                     \
        }                                                                       \
    } while (0)

// ---------------- step 0: code0 = argmin ||x - cb0_k||^2 ----------------
__global__ void k_code0(const float* __restrict__ x,
                        const float* __restrict__ cb0,
                        float* __restrict__ out) {
    __shared__ float s_x[Dq];
    __shared__ float s_v[256];
    __shared__ int   s_i[256];
    int b = blockIdx.x, t = threadIdx.x;
    if (t < Dq) s_x[t] = x[b * Dq + t];
    __syncthreads();
    const float* c = cb0 + t * Dq;
    float acc1 = 0.f, acc2 = 0.f;
    #pragma unroll 8
    for (int d = 0; d < Dq; d++) {
        float cv = c[d];
        acc1 = fmaf(cv, cv, acc1);
        acc2 = fmaf(s_x[d], cv, acc2);
    }
    s_v[t] = acc1 - 2.f * acc2;
    s_i[t] = t;
    __syncthreads();
    for (int s = 128; s > 0; s >>= 1) {
        if (t < s) {
            float v2 = s_v[t + s]; int i2 = s_i[t + s];
            if (v2 < s_v[t] || (v2 == s_v[t] && i2 < s_i[t])) { s_v[t] = v2; s_i[t] = i2; }
        }
        __syncthreads();
    }
    int idx = s_i[0];
    if (t < Dq) {
        float v = cb0[idx * Dq + t];
        g_xhat[b * Dq + t] = v;
        out[OUT_SIDE + b * Dq + t] = v;   // side[0]
    }
    if (t == 0) out[OUT_CODES + b * Mq + 0] = (float)idx;
}

// ---------------- generic 128-deep GEMM core (structure cloned from R9 gemmB) ----
// out[row0+r][col0+c] = sum_{d=0..127} A[(row0+r)*lda + d] * W[(col0+c)*ldw + d]
// optional += addA[(row0+r)*lda + col0+c], += bias[col0+c]
__device__ __forceinline__ void gemm128_core(
    const float* __restrict__ A, int lda,
    const float* __restrict__ W, int ldw,
    const float* __restrict__ addA,
    const float* __restrict__ bias,
    float* __restrict__ out, int ldo,
    int row0, int col0)
{
    __shared__ __align__(16) float As_s[16][132];
    __shared__ __align__(16) float Ws_s[16][132];
    int tid = threadIdx.x;
    int tx = tid & 15, ty = tid >> 4;
    unsigned long long acc[8][4] = {};
    for (int dd = 0; dd < 128; dd += 16) {
        #pragma unroll
        for (int it = 0; it < 8; it++) {
            int idx = tid + it * 256;
            int r = idx >> 4, d = idx & 15;
            As_s[d][r] = A[(row0 + r) * lda + dd + d];
        }
        #pragma unroll
        for (int it = 0; it < 8; it++) {
            int idx = tid + it * 256;
            int c = idx >> 4, d = idx & 15;
            Ws_s[d][c] = W[(col0 + c) * ldw + dd + d];
        }
        __syncthreads();
        #pragma unroll
        for (int h = 0; h < 16; h++) INNER_STEP(As_s, Ws_s);
        __syncthreads();
    }
    #pragma unroll
    for (int i = 0; i < 8; i++) {
        int r = row0 + ty * 8 + i;
        int c0 = col0 + tx * 8;
        float2 p0 = unpk2(acc[i][0]), p1 = unpk2(acc[i][1]);
        float2 p2 = unpk2(acc[i][2]), p3 = unpk2(acc[i][3]);
        float v[8] = {p0.x, p0.y, p1.x, p1.y, p2.x, p2.y, p3.x, p3.y};
        if (addA) {
            #pragma unroll
            for (int j = 0; j < 8; j++) v[j] += addA[r * lda + c0 + j];
        }
        if (bias) {
            #pragma unroll
            for (int j = 0; j < 8; j++) v[j] += bias[c0 + j];
        }
        *(float4*)(&out[r * ldo + c0])     = make_float4(v[0], v[1], v[2], v[3]);
        *(float4*)(&out[r * ldo + c0 + 4]) = make_float4(v[4], v[5], v[6], v[7]);
    }
}

// ---- prep wrappers (device globals indexed inside; no host symbol addresses) ----
// CkAll[m] = cb[m] + cb[m] @ Wz[m]^T      grid (2,1,7)
__global__ __launch_bounds__(256) void k_prep_ck(const float* __restrict__ cbs,
                                                 const float* __restrict__ Wc) {
    long z = blockIdx.z;
    const float* cb = cbs + z * (Kq * Dq);
    gemm128_core(cb, Dq,
                 Wc + z * (Dq * 2 * Dq), 2 * Dq,
                 /*addA=*/cb, /*bias=*/nullptr,
                 g_CkAll + z * (Kq * Dq), Dq,
                 blockIdx.x * 128, 0);
}
// A0All[m] = CkAll[m] @ W1[m][0]^T        grid (2,2,7)
__global__ __launch_bounds__(256) void k_prep_a0(const float* __restrict__ W1) {
    long z = blockIdx.z;
    gemm128_core(g_CkAll + z * (Kq * Dq), Dq,
                 W1 + z * (2 * Hq * Dq), Dq,
                 nullptr, nullptr,
                 g_A0All + z * (Kq * Hq), Hq,
                 blockIdx.x * 128, blockIdx.y * 128);
}
// Xb = xhat @ Wx^T + bc                   grid (8,1,1)
__global__ __launch_bounds__(256) void k_prep_xb(const float* __restrict__ Wx,
                                                 const float* __restrict__ bcm) {
    gemm128_core(g_xhat, Dq, Wx, 2 * Dq, nullptr, bcm,
                 g_Xb, Dq, blockIdx.x * 128, 0);
}
// B0 = Xb @ W10^T                         grid (8,2,1)
__global__ __launch_bounds__(256) void k_prep_b0(const float* __restrict__ W10) {
    gemm128_core(g_Xb, Dq, W10, Dq, nullptr, nullptr,
                 g_B0, Hq, blockIdx.x * 128, blockIdx.y * 128);
}

// ---------------- GEMM A: Z1 = Ck+Xb + relu(A0+B0) @ W2_0^T  (R9-proven body) ----
__global__ __launch_bounds__(256) void gemmA(int m, const float* __restrict__ W20) {
    __shared__ __align__(16) float Rs[16][132];
    __shared__ __align__(16) float Ws[16][132];
    int bx = blockIdx.x;              // 0..2047
    int b  = bx >> 1;
    int k0 = (bx & 1) * 128;
    int row0 = b * Kq + k0;
    int tid = threadIdx.x;
    int tx = tid & 15, ty = tid >> 4;
    unsigned long long acc[8][4] = {};
    const float* A0p = g_A0All + (long)m * Kq * Hq + k0 * Hq;
    const float* B0p = g_B0 + b * Hq;
    for (int kk = 0; kk < Hq; kk += 16) {
        #pragma unroll
        for (int it = 0; it < 8; it++) {
            int idx = tid + it * 256;
            int r = idx >> 4, h = idx & 15;
            float v = A0p[r * Hq + kk + h] + B0p[kk + h];
            Rs[h][r] = fmaxf(v, 0.f);
        }
        #pragma unroll
        for (int it = 0; it < 8; it++) {
            int idx = tid + it * 256;
            int d = idx >> 4, h = idx & 15;
            Ws[h][d] = W20[d * Hq + kk + h];
        }
        __syncthreads();
        #pragma unroll
        for (int h = 0; h < 16; h++) INNER_STEP(Rs, Ws);
        __syncthreads();
    }
    const float* Ckp = g_CkAll + (long)m * Kq * Dq + k0 * Dq;
    const float* Xbp = g_Xb + b * Dq;
    #pragma unroll
    for (int i = 0; i < 8; i++) {
        int r = ty * 8 + i;
        int base = (row0 + r) * Dq + tx * 8;
        const float* ck = Ckp + r * Dq + tx * 8;
        const float* xb = Xbp + tx * 8;
        float2 p0 = unpk2(acc[i][0]), p1 = unpk2(acc[i][1]);
        float2 p2 = unpk2(acc[i][2]), p3 = unpk2(acc[i][3]);
        float4 o0 = make_float4(p0.x + ck[0] + xb[0], p0.y + ck[1] + xb[1],
                                p1.x + ck[2] + xb[2], p1.y + ck[3] + xb[3]);
        float4 o1 = make_float4(p2.x + ck[4] + xb[4], p2.y + ck[5] + xb[5],
                                p3.x + ck[6] + xb[6], p3.y + ck[7] + xb[7]);
        *(float4*)(&g_Z1[base])     = o0;
        *(float4*)(&g_Z1[base + 4]) = o1;
    }
}

// ---------------- GEMM B: H1 = relu(Z1 @ W1_1^T)  (R9-proven body) ----------------
__global__ __launch_bounds__(256) void gemmB(const float* __restrict__ W11) {
    __shared__ __align__(16) float Zs[16][132];
    __shared__ __align__(16) float W1s[16][132];
    int bx = blockIdx.x;
    int row0 = (bx >> 1) * 128;
    int h0   = (bx & 1) * 128;
    int tid = threadIdx.x;
    int tx = tid & 15, ty = tid >> 4;
    unsigned long long acc[8][4] = {};
    for (int dd = 0; dd < Dq; dd += 16) {
        #pragma unroll
        for (int it = 0; it < 8; it++) {
            int idx = tid + it * 256;
            int r = idx >> 4, d = idx & 15;
            Zs[d][r] = g_Z1[(row0 + r) * Dq + dd + d];
        }
        #pragma unroll
        for (int it = 0; it < 8; it++) {
            int idx = tid + it * 256;
            int c = idx >> 4, d = idx & 15;
            W1s[d][c] = W11[(h0 + c) * Dq + dd + d];
        }
        __syncthreads();
        #pragma unroll
        for (int h = 0; h < 16; h++) INNER_STEP(Zs, W1s);
        __syncthreads();
    }
    #pragma unroll
    for (int i = 0; i < 8; i++) {
        int r = ty * 8 + i;
        int base = (row0 + r) * Hq + h0 + tx * 8;
        float2 p0 = unpk2(acc[i][0]), p1 = unpk2(acc[i][1]);
        float2 p2 = unpk2(acc[i][2]), p3 = unpk2(acc[i][3]);
        float4 o0 = make_float4(fmaxf(p0.x, 0.f), fmaxf(p0.y, 0.f),
                                fmaxf(p1.x, 0.f), fmaxf(p1.y, 0.f));
        float4 o1 = make_float4(fmaxf(p2.x, 0.f), fmaxf(p2.y, 0.f),
                                fmaxf(p3.x, 0.f), fmaxf(p3.y, 0.f));
        *(float4*)(&g_H1[base])     = o0;
        *(float4*)(&g_H1[base + 4]) = o1;
    }
}

// ---------------- GEMM C: ZF = Z1 + H1 @ W2_1^T + xhat; dist  (R9-proven body) ----
__global__ __launch_bounds__(256) void gemmC(const float* __restrict__ x,
                                             const float* __restrict__ W21) {
    __shared__ __align__(16) float Hs[16][132];
    __shared__ __align__(16) float Ws[16][132];
    __shared__ float s_ssq[128][17];
    __shared__ float s_sxz[128][17];
    __shared__ float s_x[Dq];
    __shared__ float s_xh[Dq];
    int bx = blockIdx.x;              // 0..2047
    int row0 = bx * 128;
    int b = bx >> 1;
    int tid = threadIdx.x;
    int tx = tid & 15, ty = tid >> 4;
    if (tid < Dq) { s_x[tid] = x[b * Dq + tid]; s_xh[tid] = g_xhat[b * Dq + tid]; }
    unsigned long long acc[8][4] = {};
    for (int kk = 0; kk < Hq; kk += 16) {
        #pragma unroll
        for (int it = 0; it < 8; it++) {
            int idx = tid + it * 256;
            int r = idx >> 4, h = idx & 15;
            Hs[h][r] = g_H1[(row0 + r) * Hq + kk + h];
        }
        #pragma unroll
        for (int it = 0; it < 8; it++) {
            int idx = tid + it * 256;
            int d = idx >> 4, h = idx & 15;
            Ws[h][d] = W21[d * Hq + kk + h];
        }
        __syncthreads();
        #pragma unroll
        for (int h = 0; h < 16; h++) INNER_STEP(Hs, Ws);
        __syncthreads();
    }
    #pragma unroll
    for (int i = 0; i < 8; i++) {
        int r = ty * 8 + i;
        int base = (row0 + r) * Dq + tx * 8;
        float ssq = 0.f, sxz = 0.f;
        float zf[8];
        float2 p[4] = {unpk2(acc[i][0]), unpk2(acc[i][1]), unpk2(acc[i][2]), unpk2(acc[i][3])};
        #pragma unroll
        for (int jp = 0; jp < 4; jp++) {
            int j0 = jp * 2;
            float v0 = p[jp].x + g_Z1[base + j0]     + s_xh[tx * 8 + j0];
            float v1 = p[jp].y + g_Z1[base + j0 + 1] + s_xh[tx * 8 + j0 + 1];
            zf[j0] = v0; zf[j0 + 1] = v1;
            ssq = fmaf(v0, v0, fmaf(v1, v1, ssq));
            sxz = fmaf(s_x[tx * 8 + j0], v0, fmaf(s_x[tx * 8 + j0 + 1], v1, sxz));
        }
        *(float4*)(&g_ZF[base])     = make_float4(zf[0], zf[1], zf[2], zf[3]);
        *(float4*)(&g_ZF[base + 4]) = make_float4(zf[4], zf[5], zf[6], zf[7]);
        s_ssq[r][tx] = ssq;
        s_sxz[r][tx] = sxz;
    }
    __syncthreads();
    if (tid < 128) {
        float ssq = 0.f, sxz = 0.f;
        #pragma unroll
        for (int t = 0; t < 16; t++) { ssq += s_ssq[tid][t]; sxz += s_sxz[tid][t]; }
        g_dist[row0 + tid] = ssq - 2.f * sxz;
    }
}

// ---------------- select ----------------
__global__ void k_select(float* __restrict__ out, int m) {
    __shared__ float s_v[256];
    __shared__ int   s_i[256];
    int b = blockIdx.x, t = threadIdx.x;
    s_v[t] = g_dist[b * Kq + t];
    s_i[t] = t;
    __syncthreads();
    for (int s = 128; s > 0; s >>= 1) {
        if (t < s) {
            float v2 = s_v[t + s]; int i2 = s_i[t + s];
            if (v2 < s_v[t] || (v2 == s_v[t] && i2 < s_i[t])) { s_v[t] = v2; s_i[t] = i2; }
        }
        __syncthreads();
    }
    int idx = s_i[0];
    if (t < Dq) {
        float v = g_ZF[(b * Kq + idx) * Dq + t];
        g_xhat[b * Dq + t] = v;
        out[OUT_SIDE + (m + 1) * (BSq * Dq) + b * Dq + t] = v;
        if (m == Mq - 2) out[b * Dq + t] = v;
    }
    if (t == 0) out[OUT_CODES + b * Mq + m + 1] = (float)idx;
}

// ---------------- launch (pure kernel launches, R9-style) ----------------
extern "C" void kernel_launch(void* const* d_in, const int* in_sizes, int n_in,
                              void* d_out, int out_size) {
    const float* x   = (const float*)d_in[0];   // [1024,128]
    const float* cb0 = (const float*)d_in[1];   // [256,128]
    const float* cbs = (const float*)d_in[2];   // [7,256,128]
    const float* Wc  = (const float*)d_in[3];   // [7,128,256]
    const float* bc  = (const float*)d_in[4];   // [7,128]
    const float* W1  = (const float*)d_in[5];   // [7,2,256,128]
    const float* W2  = (const float*)d_in[6];   // [7,2,128,256]
    float* out = (float*)d_out;

    k_code0<<<BSq, 256>>>(x, cb0, out);

    // Hoisted (xhat-independent) per-m precomputation.
    k_prep_ck<<<dim3(2, 1, Mq - 1), 256>>>(cbs, Wc);
    k_prep_a0<<<dim3(2, 2, Mq - 1), 256>>>(W1);

    for (int m = 0; m < Mq - 1; m++) {
        const float* Wcm = Wc + m * Dq * (2 * Dq);
        const float* bcm = bc + m * Dq;
        const float* W10 = W1 + (m * 2 + 0) * Hq * Dq;
        const float* W11 = W1 + (m * 2 + 1) * Hq * Dq;
        const float* W20 = W2 + (m * 2 + 0) * Dq * Hq;
        const float* W21 = W2 + (m * 2 + 1) * Dq * Hq;

        k_prep_xb<<<dim3(8, 1, 1), 256>>>(Wcm + Dq, bcm);
        k_prep_b0<<<dim3(8, 2, 1), 256>>>(W10);

        gemmA<<<2048, 256>>>(m, W20);
        gemmB<<<4096, 256>>>(W11);
        gemmC<<<2048, 256>>>(x, W21);
        k_select<<<BSq, 256>>>(out, m);
    }
}

// round 15
// speedup vs baseline: 1.7792x; 1.7792x over previous
#include <cuda_runtime.h>
#include <cstdint>

// QINCo: D=128, M=8, K=256, L=2, H=256, BS=1024
#define Dq   128
#define Mq   8
#define Kq   256
#define Hq   256
#define BSq  1024
#define NROW (BSq * Kq)

#define OUT_CODES (BSq * Dq)
#define OUT_SIDE  (OUT_CODES + BSq * Mq)

// ---------------- device scratch (static, no allocs) ----------------
__device__ float g_xhat[BSq * Dq];
__device__ float g_CkAll[(Mq - 1) * Kq * Dq];    // per-m: cb + cb@Wz^T
__device__ float g_A0All[(Mq - 1) * Kq * Hq];    // per-m: Ck@W1_0^T
__device__ float g_Xb[BSq * Dq];
__device__ float g_B0[BSq * Hq];
__device__ float g_Z1[NROW * Dq];
__device__ float g_H1[NROW * Hq];
__device__ float g_ZF[NROW * Dq];
__device__ float g_dist[NROW];

// ---------------- packed f32x2 helpers ----------------
__device__ __forceinline__ void ffma2(unsigned long long& d, unsigned long long a, unsigned long long b) {
    asm("fma.rn.f32x2 %0, %1, %2, %0;" : "+l"(d) : "l"(a), "l"(b));
}
__device__ __forceinline__ unsigned long long bcast2(float v) {
    unsigned long long r;
    asm("mov.b64 %0, {%1, %1};" : "=l"(r) : "f"(v));
    return r;
}
__device__ __forceinline__ float2 unpk2(unsigned long long v) {
    float lo, hi;
    asm("mov.b64 {%0, %1}, %2;" : "=f"(lo), "=f"(hi) : "l"(v));
    return make_float2(lo, hi);
}

// ================= FFMA2 inner-product step (PROVEN) =================
#define INNER_STEP(Rsrc, Wsrc)                                                  \
    do {                                                                        \
        float4 a0 = *(const float4*)(&(Rsrc)[h][ty * 8]);                       \
        float4 a1 = *(const float4*)(&(Rsrc)[h][ty * 8 + 4]);                   \
        ulonglong2 wv0 = *(const ulonglong2*)(&(Wsrc)[h][tx * 8]);              \
        ulonglong2 wv1 = *(const ulonglong2*)(&(Wsrc)[h][tx * 8 + 4]);          \
        unsigned long long ap[8] = {bcast2(a0.x), bcast2(a0.y), bcast2(a0.z),   \
                                    bcast2(a0.w), bcast2(a1.x), bcast2(a1.y),   \
                                    bcast2(a1.z), bcast2(a1.w)};                \
        unsigned long long wp[4] = {wv0.x, wv0.y, wv1.x, wv1.y};                \
        _Pragma("unroll")                                                       \
        for (int i = 0; i < 8; i++) {                                           \
            ffma2(acc[i][0], ap[i], wp[0]);                                     \
            ffma2(acc[i][1], ap[i], wp[1]);                                     \
            ffma2(acc[i][2], ap[i], wp[2]);                                     \
            ffma2(acc[i][3], ap[i], wp[3]);                                     \
        }                                                                       \
    } while (0)

// ---- pipelined staging macros (all do{}while(0); pragmas inside braces) ----
// Load a [128 x 16] A-chunk into 2 float4 regs (coalesced).
#define LDG_CHUNK(pa, Asrc, lda, kk)                                            \
    do {                                                                        \
        _Pragma("unroll")                                                       \
        for (int it_ = 0; it_ < 2; it_++) {                                     \
            int f_ = tid + it_ * 256; int r_ = f_ >> 2, q_ = f_ & 3;            \
            pa[it_] = *(const float4*)((Asrc) + r_ * (lda) + (kk) + q_ * 4);    \
        }                                                                       \
    } while (0)

// Store prefetched A regs transposed (k-major) into one 16-deep buffer.
#define STS_CHUNK(pa, buf)                                                      \
    do {                                                                        \
        _Pragma("unroll")                                                       \
        for (int it_ = 0; it_ < 2; it_++) {                                     \
            int f_ = tid + it_ * 256; int r_ = f_ >> 2, q_ = f_ & 3;            \
            (buf)[q_ * 4 + 0][r_] = pa[it_].x;                                  \
            (buf)[q_ * 4 + 1][r_] = pa[it_].y;                                  \
            (buf)[q_ * 4 + 2][r_] = pa[it_].z;                                  \
            (buf)[q_ * 4 + 3][r_] = pa[it_].w;                                  \
        }                                                                       \
    } while (0)

// Store with broadcast-row add + relu (gemmA: relu(A0[k]+B0[b])).
#define STS_CHUNK_RELU(pa, buf, B0p, kk)                                        \
    do {                                                                        \
        _Pragma("unroll")                                                       \
        for (int it_ = 0; it_ < 2; it_++) {                                     \
            int f_ = tid + it_ * 256; int r_ = f_ >> 2, q_ = f_ & 3;            \
            float4 bv_ = *(const float4*)((B0p) + (kk) + q_ * 4);               \
            (buf)[q_ * 4 + 0][r_] = fmaxf(pa[it_].x + bv_.x, 0.f);              \
            (buf)[q_ * 4 + 1][r_] = fmaxf(pa[it_].y + bv_.y, 0.f);              \
            (buf)[q_ * 4 + 2][r_] = fmaxf(pa[it_].z + bv_.z, 0.f);              \
            (buf)[q_ * 4 + 3][r_] = fmaxf(pa[it_].w + bv_.w, 0.f);              \
        }                                                                       \
    } while (0)

// W chunk: [128 cols x 16 k], LDG + transposed STS (L2-hot).
#define STAGE_W16(Wp, ldw, kk, buf)                                             \
    do {                                                                        \
        _Pragma("unroll")                                                       \
        for (int it_ = 0; it_ < 2; it_++) {                                     \
            int f_ = tid + it_ * 256; int c_ = f_ >> 2, q_ = f_ & 3;            \
            float4 w_ = *(const float4*)((Wp) + c_ * (ldw) + (kk) + q_ * 4);    \
            (buf)[q_ * 4 + 0][c_] = w_.x;                                       \
            (buf)[q_ * 4 + 1][c_] = w_.y;                                       \
            (buf)[q_ * 4 + 2][c_] = w_.z;                                       \
            (buf)[q_ * 4 + 3][c_] = w_.w;                                       \
        }                                                                       \
    } while (0)

// ---------------- step 0: code0 = argmin ||x - cb0_k||^2 ----------------
__global__ void k_code0(const float* __restrict__ x,
                        const float* __restrict__ cb0,
                        float* __restrict__ out) {
    __shared__ float s_x[Dq];
    __shared__ float s_v[256];
    __shared__ int   s_i[256];
    int b = blockIdx.x, t = threadIdx.x;
    if (t < Dq) s_x[t] = x[b * Dq + t];
    __syncthreads();
    const float* c = cb0 + t * Dq;
    float acc1 = 0.f, acc2 = 0.f;
    #pragma unroll 8
    for (int d = 0; d < Dq; d++) {
        float cv = c[d];
        acc1 = fmaf(cv, cv, acc1);
        acc2 = fmaf(s_x[d], cv, acc2);
    }
    s_v[t] = acc1 - 2.f * acc2;
    s_i[t] = t;
    __syncthreads();
    for (int s = 128; s > 0; s >>= 1) {
        if (t < s) {
            float v2 = s_v[t + s]; int i2 = s_i[t + s];
            if (v2 < s_v[t] || (v2 == s_v[t] && i2 < s_i[t])) { s_v[t] = v2; s_i[t] = i2; }
        }
        __syncthreads();
    }
    int idx = s_i[0];
    if (t < Dq) {
        float v = cb0[idx * Dq + t];
        g_xhat[b * Dq + t] = v;
        out[OUT_SIDE + b * Dq + t] = v;   // side[0]
    }
    if (t == 0) out[OUT_CODES + b * Mq + 0] = (float)idx;
}

// ---------------- generic 128-deep GEMM core (prep; PROVEN in R14) ----------------
__device__ __forceinline__ void gemm128_core(
    const float* __restrict__ A, int lda,
    const float* __restrict__ W, int ldw,
    const float* __restrict__ addA,
    const float* __restrict__ bias,
    float* __restrict__ out, int ldo,
    int row0, int col0)
{
    __shared__ __align__(16) float As_s[16][132];
    __shared__ __align__(16) float Ws_s[16][132];
    int tid = threadIdx.x;
    int tx = tid & 15, ty = tid >> 4;
    unsigned long long acc[8][4] = {};
    for (int dd = 0; dd < 128; dd += 16) {
        #pragma unroll
        for (int it = 0; it < 8; it++) {
            int idx = tid + it * 256;
            int r = idx >> 4, d = idx & 15;
            As_s[d][r] = A[(row0 + r) * lda + dd + d];
        }
        #pragma unroll
        for (int it = 0; it < 8; it++) {
            int idx = tid + it * 256;
            int c = idx >> 4, d = idx & 15;
            Ws_s[d][c] = W[(col0 + c) * ldw + dd + d];
        }
        __syncthreads();
        #pragma unroll
        for (int h = 0; h < 16; h++) INNER_STEP(As_s, Ws_s);
        __syncthreads();
    }
    #pragma unroll
    for (int i = 0; i < 8; i++) {
        int r = row0 + ty * 8 + i;
        int c0 = col0 + tx * 8;
        float2 p0 = unpk2(acc[i][0]), p1 = unpk2(acc[i][1]);
        float2 p2 = unpk2(acc[i][2]), p3 = unpk2(acc[i][3]);
        float v[8] = {p0.x, p0.y, p1.x, p1.y, p2.x, p2.y, p3.x, p3.y};
        if (addA) {
            #pragma unroll
            for (int j = 0; j < 8; j++) v[j] += addA[r * lda + c0 + j];
        }
        if (bias) {
            #pragma unroll
            for (int j = 0; j < 8; j++) v[j] += bias[c0 + j];
        }
        *(float4*)(&out[r * ldo + c0])     = make_float4(v[0], v[1], v[2], v[3]);
        *(float4*)(&out[r * ldo + c0 + 4]) = make_float4(v[4], v[5], v[6], v[7]);
    }
}

// ---- prep wrappers ----
__global__ __launch_bounds__(256) void k_prep_ck(const float* __restrict__ cbs,
                                                 const float* __restrict__ Wc) {
    long z = blockIdx.z;
    const float* cb = cbs + z * (Kq * Dq);
    gemm128_core(cb, Dq, Wc + z * (Dq * 2 * Dq), 2 * Dq,
                 cb, nullptr, g_CkAll + z * (Kq * Dq), Dq,
                 blockIdx.x * 128, 0);
}
__global__ __launch_bounds__(256) void k_prep_a0(const float* __restrict__ W1) {
    long z = blockIdx.z;
    gemm128_core(g_CkAll + z * (Kq * Dq), Dq, W1 + z * (2 * Hq * Dq), Dq,
                 nullptr, nullptr, g_A0All + z * (Kq * Hq), Hq,
                 blockIdx.x * 128, blockIdx.y * 128);
}
__global__ __launch_bounds__(256) void k_prep_xb(const float* __restrict__ Wx,
                                                 const float* __restrict__ bcm) {
    gemm128_core(g_xhat, Dq, Wx, 2 * Dq, nullptr, bcm,
                 g_Xb, Dq, blockIdx.x * 128, 0);
}
__global__ __launch_bounds__(256) void k_prep_b0(const float* __restrict__ W10) {
    gemm128_core(g_Xb, Dq, W10, Dq, nullptr, nullptr,
                 g_B0, Hq, blockIdx.x * 128, blockIdx.y * 128);
}

// ---------------- GEMM A: Z1 = Ck+Xb + relu(A0+B0) @ W2_0^T (pipelined) ----------
__global__ __launch_bounds__(256, 2) void gemmA(int m, const float* __restrict__ W20) {
    __shared__ __align__(16) float As[2][16][132];
    __shared__ __align__(16) float Ws[2][16][132];
    int bx = blockIdx.x;
    int b  = bx >> 1;
    int k0 = (bx & 1) * 128;
    int row0 = b * Kq + k0;
    int tid = threadIdx.x, tx = tid & 15, ty = tid >> 4;
    unsigned long long acc[8][4] = {};
    const float* A0p = g_A0All + (long)m * Kq * Hq + k0 * Hq;
    const float* B0p = g_B0 + b * Hq;
    float4 pa[2];
    LDG_CHUNK(pa, A0p, Hq, 0);
    STS_CHUNK_RELU(pa, As[0], B0p, 0);
    STAGE_W16(W20, Hq, 0, Ws[0]);
    __syncthreads();
    for (int c = 0; c < 16; c++) {
        int cb = c & 1;
        if (c < 15) LDG_CHUNK(pa, A0p, Hq, (c + 1) * 16);
        #pragma unroll
        for (int h = 0; h < 16; h++) INNER_STEP(As[cb], Ws[cb]);
        if (c < 15) {
            STS_CHUNK_RELU(pa, As[cb ^ 1], B0p, (c + 1) * 16);
            STAGE_W16(W20, Hq, (c + 1) * 16, Ws[cb ^ 1]);
            __syncthreads();
        }
    }
    const float* Ckp = g_CkAll + (long)m * Kq * Dq + k0 * Dq;
    const float* Xbp = g_Xb + b * Dq;
    #pragma unroll
    for (int i = 0; i < 8; i++) {
        int r = ty * 8 + i;
        int base = (row0 + r) * Dq + tx * 8;
        const float* ck = Ckp + r * Dq + tx * 8;
        const float* xb = Xbp + tx * 8;
        float2 p0 = unpk2(acc[i][0]), p1 = unpk2(acc[i][1]);
        float2 p2 = unpk2(acc[i][2]), p3 = unpk2(acc[i][3]);
        float4 o0 = make_float4(p0.x + ck[0] + xb[0], p0.y + ck[1] + xb[1],
                                p1.x + ck[2] + xb[2], p1.y + ck[3] + xb[3]);
        float4 o1 = make_float4(p2.x + ck[4] + xb[4], p2.y + ck[5] + xb[5],
                                p3.x + ck[6] + xb[6], p3.y + ck[7] + xb[7]);
        *(float4*)(&g_Z1[base])     = o0;
        *(float4*)(&g_Z1[base + 4]) = o1;
    }
}

// ---------------- GEMM B: H1 = relu(Z1 @ W1_1^T) (pipelined) ----------------
__global__ __launch_bounds__(256, 2) void gemmB(const float* __restrict__ W11) {
    __shared__ __align__(16) float As[2][16][132];
    __shared__ __align__(16) float Ws[2][16][132];
    int bx = blockIdx.x;
    int row0 = (bx >> 1) * 128;
    int h0   = (bx & 1) * 128;
    int tid = threadIdx.x, tx = tid & 15, ty = tid >> 4;
    unsigned long long acc[8][4] = {};
    const float* Asrc = g_Z1 + row0 * Dq;
    const float* Wp   = W11 + h0 * Dq;
    float4 pa[2];
    LDG_CHUNK(pa, Asrc, Dq, 0);
    STS_CHUNK(pa, As[0]);
    STAGE_W16(Wp, Dq, 0, Ws[0]);
    __syncthreads();
    for (int c = 0; c < 8; c++) {
        int cb = c & 1;
        if (c < 7) LDG_CHUNK(pa, Asrc, Dq, (c + 1) * 16);
        #pragma unroll
        for (int h = 0; h < 16; h++) INNER_STEP(As[cb], Ws[cb]);
        if (c < 7) {
            STS_CHUNK(pa, As[cb ^ 1]);
            STAGE_W16(Wp, Dq, (c + 1) * 16, Ws[cb ^ 1]);
            __syncthreads();
        }
    }
    #pragma unroll
    for (int i = 0; i < 8; i++) {
        int r = ty * 8 + i;
        int base = (row0 + r) * Hq + h0 + tx * 8;
        float2 p0 = unpk2(acc[i][0]), p1 = unpk2(acc[i][1]);
        float2 p2 = unpk2(acc[i][2]), p3 = unpk2(acc[i][3]);
        float4 o0 = make_float4(fmaxf(p0.x, 0.f), fmaxf(p0.y, 0.f),
                                fmaxf(p1.x, 0.f), fmaxf(p1.y, 0.f));
        float4 o1 = make_float4(fmaxf(p2.x, 0.f), fmaxf(p2.y, 0.f),
                                fmaxf(p3.x, 0.f), fmaxf(p3.y, 0.f));
        *(float4*)(&g_H1[base])     = o0;
        *(float4*)(&g_H1[base + 4]) = o1;
    }
}

// ---------------- GEMM C: ZF = Z1 + H1 @ W2_1^T + xhat; dist (pipelined) ----------
__global__ __launch_bounds__(256, 2) void gemmC(const float* __restrict__ x,
                                                const float* __restrict__ W21) {
    __shared__ __align__(16) float pool[2 * 16 * 132 * 2];  // As(2)+Ws(2): 33792 B
    __shared__ float s_x[Dq];
    __shared__ float s_xh[Dq];
    float (*As)[16][132] = (float(*)[16][132])pool;
    float (*Ws)[16][132] = (float(*)[16][132])(pool + 2 * 16 * 132);
    int bx = blockIdx.x;
    int row0 = bx * 128;
    int b = bx >> 1;
    int tid = threadIdx.x, tx = tid & 15, ty = tid >> 4;
    if (tid < Dq) { s_x[tid] = x[b * Dq + tid]; s_xh[tid] = g_xhat[b * Dq + tid]; }
    unsigned long long acc[8][4] = {};
    const float* Asrc = g_H1 + row0 * Hq;
    float4 pa[2];
    LDG_CHUNK(pa, Asrc, Hq, 0);
    STS_CHUNK(pa, As[0]);
    STAGE_W16(W21, Hq, 0, Ws[0]);
    __syncthreads();
    for (int c = 0; c < 16; c++) {
        int cb = c & 1;
        if (c < 15) LDG_CHUNK(pa, Asrc, Hq, (c + 1) * 16);
        #pragma unroll
        for (int h = 0; h < 16; h++) INNER_STEP(As[cb], Ws[cb]);
        if (c < 15) {
            STS_CHUNK(pa, As[cb ^ 1]);
            STAGE_W16(W21, Hq, (c + 1) * 16, Ws[cb ^ 1]);
            __syncthreads();
        }
    }
    // reuse pool for the per-row distance reduction (compute fully done)
    __syncthreads();
    float (*s_ssq)[17] = (float(*)[17])pool;
    float (*s_sxz)[17] = (float(*)[17])(pool + 128 * 17);
    #pragma unroll
    for (int i = 0; i < 8; i++) {
        int r = ty * 8 + i;
        int base = (row0 + r) * Dq + tx * 8;
        float ssq = 0.f, sxz = 0.f;
        float zf[8];
        float2 p[4] = {unpk2(acc[i][0]), unpk2(acc[i][1]), unpk2(acc[i][2]), unpk2(acc[i][3])};
        #pragma unroll
        for (int jp = 0; jp < 4; jp++) {
            int j0 = jp * 2;
            float v0 = p[jp].x + g_Z1[base + j0]     + s_xh[tx * 8 + j0];
            float v1 = p[jp].y + g_Z1[base + j0 + 1] + s_xh[tx * 8 + j0 + 1];
            zf[j0] = v0; zf[j0 + 1] = v1;
            ssq = fmaf(v0, v0, fmaf(v1, v1, ssq));
            sxz = fmaf(s_x[tx * 8 + j0], v0, fmaf(s_x[tx * 8 + j0 + 1], v1, sxz));
        }
        *(float4*)(&g_ZF[base])     = make_float4(zf[0], zf[1], zf[2], zf[3]);
        *(float4*)(&g_ZF[base + 4]) = make_float4(zf[4], zf[5], zf[6], zf[7]);
        s_ssq[r][tx] = ssq;
        s_sxz[r][tx] = sxz;
    }
    __syncthreads();
    if (tid < 128) {
        float ssq = 0.f, sxz = 0.f;
        #pragma unroll
        for (int t = 0; t < 16; t++) { ssq += s_ssq[tid][t]; sxz += s_sxz[tid][t]; }
        g_dist[row0 + tid] = ssq - 2.f * sxz;
    }
}

// ---------------- select ----------------
__global__ void k_select(float* __restrict__ out, int m) {
    __shared__ float s_v[256];
    __shared__ int   s_i[256];
    int b = blockIdx.x, t = threadIdx.x;
    s_v[t] = g_dist[b * Kq + t];
    s_i[t] = t;
    __syncthreads();
    for (int s = 128; s > 0; s >>= 1) {
        if (t < s) {
            float v2 = s_v[t + s]; int i2 = s_i[t + s];
            if (v2 < s_v[t] || (v2 == s_v[t] && i2 < s_i[t])) { s_v[t] = v2; s_i[t] = i2; }
        }
        __syncthreads();
    }
    int idx = s_i[0];
    if (t < Dq) {
        float v = g_ZF[(b * Kq + idx) * Dq + t];
        g_xhat[b * Dq + t] = v;
        out[OUT_SIDE + (m + 1) * (BSq * Dq) + b * Dq + t] = v;
        if (m == Mq - 2) out[b * Dq + t] = v;
    }
    if (t == 0) out[OUT_CODES + b * Mq + m + 1] = (float)idx;
}

// ---------------- launch (pure kernel launches) ----------------
extern "C" void kernel_launch(void* const* d_in, const int* in_sizes, int n_in,
                              void* d_out, int out_size) {
    const float* x   = (const float*)d_in[0];   // [1024,128]
    const float* cb0 = (const float*)d_in[1];   // [256,128]
    const float* cbs = (const float*)d_in[2];   // [7,256,128]
    const float* Wc  = (const float*)d_in[3];   // [7,128,256]
    const float* bc  = (const float*)d_in[4];   // [7,128]
    const float* W1  = (const float*)d_in[5];   // [7,2,256,128]
    const float* W2  = (const float*)d_in[6];   // [7,2,128,256]
    float* out = (float*)d_out;

    k_code0<<<BSq, 256>>>(x, cb0, out);

    // Hoisted (xhat-independent) per-m precomputation.
    k_prep_ck<<<dim3(2, 1, Mq - 1), 256>>>(cbs, Wc);
    k_prep_a0<<<dim3(2, 2, Mq - 1), 256>>>(W1);

    for (int m = 0; m < Mq - 1; m++) {
        const float* Wcm = Wc + m * Dq * (2 * Dq);
        const float* bcm = bc + m * Dq;
        const float* W10 = W1 + (m * 2 + 0) * Hq * Dq;
        const float* W11 = W1 + (m * 2 + 1) * Hq * Dq;
        const float* W20 = W2 + (m * 2 + 0) * Dq * Hq;
        const float* W21 = W2 + (m * 2 + 1) * Dq * Hq;

        k_prep_xb<<<dim3(8, 1, 1), 256>>>(Wcm + Dq, bcm);
        k_prep_b0<<<dim3(8, 2, 1), 256>>>(W10);

        gemmA<<<2048, 256>>>(m, W20);
        gemmB<<<4096, 256>>>(W11);
        gemmC<<<2048, 256>>>(x, W21);
        k_select<<<BSq, 256>>>(out, m);
    }
}